// round 8
// baseline (speedup 1.0000x reference)
#include <cuda_runtime.h>

// ---------------------------------------------------------------------------
// 2-layer LSTM decoder. Round-8: round-4 structure (256 CTAs x 32 rows,
// compact float4 gate-quad weights, 4 barriers/step, fused projection) but
// 1024 threads/CTA: thread = (unit, rowgroup of 8 rows), 8 warps/SMSP.
// Extra warps share weight lines via L1 -> no extra L2 traffic, 2x hiding.
// ---------------------------------------------------------------------------

#define ULL unsigned long long
#define T_STEPS 20
#define HP 36   // h row stride (floats): 16B-aligned, broadcast LDS.128 reads
#define CP 33   // c row stride: odd -> conflict-free per-thread access
#define NT 1024

__device__ __forceinline__ ULL pack2(float x, float y) {
    ULL r; asm("mov.b64 %0, {%1, %2};" : "=l"(r) : "f"(x), "f"(y)); return r;
}
__device__ __forceinline__ float2 unpack2(ULL v) {
    float2 r; asm("mov.b64 {%0, %1}, %2;" : "=f"(r.x), "=f"(r.y) : "l"(v)); return r;
}
__device__ __forceinline__ ULL fma2(ULL a, ULL b, ULL c) {
    ULL d; asm("fma.rn.f32x2 %0, %1, %2, %3;" : "=l"(d) : "l"(a), "l"(b), "l"(c)); return d;
}
__device__ __forceinline__ float sigf(float x)  { return __fdividef(1.f, 1.f + __expf(-x)); }
__device__ __forceinline__ float tanhe(float x) { return __fdividef(2.f, 1.f + __expf(-2.f * x)) - 1.f; }

__device__ float4 g_w1q [64  * 256];          // W1 gate quads  [k][u] = (i,f,g,o)
__device__ float4 g_u1q [256 * 256 + 256];    // U1 quads
__device__ float4 g_w2q [256 * 256 + 256];    // W2 quads
__device__ float4 g_u2q [256 * 256 + 256];    // U2 quads
__device__ float2 g_pw2 [256 * 80 + 80];      // (Wmu, Wlv) pairs [k][f]
__device__ float4 g_xw1q[8192 * 256];         // xw1 quads [row][u], bias folded

__global__ void repack_kernel(const float* __restrict__ W1, const float* __restrict__ U1,
                              const float* __restrict__ W2, const float* __restrict__ U2,
                              const float* __restrict__ Wmu, const float* __restrict__ Wlv) {
    int i = blockIdx.x * blockDim.x + threadIdx.x;   // 0..65535
    int k = i >> 8, u = i & 255;
    const float* r;
    if (i < 64 * 256) {
        r = W1 + k * 1024;
        g_w1q[i] = make_float4(r[u], r[256 + u], r[512 + u], r[768 + u]);
    }
    r = U1 + k * 1024; g_u1q[i] = make_float4(r[u], r[256 + u], r[512 + u], r[768 + u]);
    r = W2 + k * 1024; g_w2q[i] = make_float4(r[u], r[256 + u], r[512 + u], r[768 + u]);
    r = U2 + k * 1024; g_u2q[i] = make_float4(r[u], r[256 + u], r[512 + u], r[768 + u]);
    if (u < 80) g_pw2[k * 80 + u] = make_float2(Wmu[k * 80 + u], Wlv[k * 80 + u]);
}

__global__ void xw1_kernel(const float* __restrict__ z1, const float* __restrict__ z2,
                           const float* __restrict__ b1) {
    __shared__ float zt[8][64];
    const int tid = threadIdx.x;
    const int rb  = blockIdx.x * 8;
    for (int i = tid; i < 512; i += 256) {
        int r = i >> 6, k = i & 63;
        zt[r][k] = (k < 32) ? z1[(rb + r) * 32 + k] : z2[(rb + r) * 32 + (k - 32)];
    }
    __syncthreads();
    const int u = tid;
    float4 acc[8];
    #pragma unroll
    for (int r = 0; r < 8; r++) acc[r] = make_float4(0.f, 0.f, 0.f, 0.f);
    for (int k = 0; k < 64; k++) {
        float4 w = g_w1q[k * 256 + u];
        #pragma unroll
        for (int r = 0; r < 8; r++) {
            float zv = zt[r][k];
            acc[r].x += zv * w.x; acc[r].y += zv * w.y;
            acc[r].z += zv * w.z; acc[r].w += zv * w.w;
        }
    }
    float4 bq = make_float4(b1[u], b1[256 + u], b1[512 + u], b1[768 + u]);
    #pragma unroll
    for (int r = 0; r < 8; r++)
        g_xw1q[(size_t)(rb + r) * 256 + u] =
            make_float4(acc[r].x + bq.x, acc[r].y + bq.y, acc[r].z + bq.z, acc[r].w + bq.w);
}

// SMEM: h1s/h2s [256][HP], c1s/c2s [256][CP]  (32 rows)
#define SMEM_FLOATS (2 * 256 * HP + 2 * 256 * CP)
#define SMEM_BYTES  (SMEM_FLOATS * 4)

__global__ void __launch_bounds__(NT, 1) lstm_kernel(
    const float* __restrict__ b2, const float* __restrict__ bmu, const float* __restrict__ blv,
    const float* __restrict__ eps, float* __restrict__ out)
{
    extern __shared__ float sm[];
    float* h1s = sm;
    float* h2s = sm + 256 * HP;
    float* c1s = sm + 2 * 256 * HP;
    float* c2s = c1s + 256 * CP;

    const int tid = threadIdx.x;
    const int u   = tid & 255;
    const int rg  = tid >> 8;       // 0..3
    const int r0  = rg * 8;         // 8 rows per thread (4 f32x2 pairs)
    const int rb  = blockIdx.x * 32;

    for (int i = tid; i < SMEM_FLOATS; i += NT) sm[i] = 0.f;
    __syncthreads();

    const float b2i = b2[u], b2f = b2[256 + u], b2g = b2[512 + u], b2o = b2[768 + u];

    // fused proj+sampler: 640 threads = 80 features x 8 row groups of 4 rows
    const bool  pact = tid < 640;
    const int   pf   = pact ? (tid % 80) : 0;
    const int   pgp  = pact ? (tid / 80) : 0;    // 0..7
    const int   pr0  = pgp * 4;
    const float pbmu = pact ? bmu[pf] : 0.f;
    const float pblv = pact ? blv[pf] : 0.f;

    const float4* xq = g_xw1q + (size_t)(rb + r0) * 256 + u;

    ULL acc[4][4];

    for (int t = 0; t < T_STEPS; t++) {
        // ================= layer 1: acc = xw1 + h1 @ U1 =================
        #pragma unroll
        for (int p = 0; p < 4; p++) {
            float4 q0 = xq[(2 * p) * 256];
            float4 q1 = xq[(2 * p + 1) * 256];
            acc[0][p] = pack2(q0.x, q1.x);
            acc[1][p] = pack2(q0.y, q1.y);
            acc[2][p] = pack2(q0.z, q1.z);
            acc[3][p] = pack2(q0.w, q1.w);
        }
        {
            const char* hb = (const char*)(h1s + r0);
            #pragma unroll 2
            for (int k = 0; k < 256; k++) {
                float4 w = g_u1q[k * 256 + u];
                const ulonglong2* hp = (const ulonglong2*)(hb + (size_t)k * (HP * 4));
                ulonglong2 a0 = hp[0], a1 = hp[1];
                ULL wi = pack2(w.x, w.x), wf = pack2(w.y, w.y);
                ULL wg = pack2(w.z, w.z), wo = pack2(w.w, w.w);
                #pragma unroll
                for (int p = 0; p < 4; p++) {
                    ULL hv = (p == 0) ? a0.x : (p == 1) ? a0.y : (p == 2) ? a1.x : a1.y;
                    acc[0][p] = fma2(hv, wi, acc[0][p]);
                    acc[1][p] = fma2(hv, wf, acc[1][p]);
                    acc[2][p] = fma2(hv, wg, acc[2][p]);
                    acc[3][p] = fma2(hv, wo, acc[3][p]);
                }
            }
        }
        __syncthreads();                                     // (1) GEMV1 reads done
        #pragma unroll
        for (int p = 0; p < 4; p++) {
            float2 iv = unpack2(acc[0][p]);
            float2 fv = unpack2(acc[1][p]);
            float2 gv = unpack2(acc[2][p]);
            float2 ov = unpack2(acc[3][p]);
            int rr = r0 + 2 * p;
            float c0 = c1s[u * CP + rr], c1 = c1s[u * CP + rr + 1];
            c0 = sigf(fv.x) * c0 + sigf(iv.x) * tanhe(gv.x);
            c1 = sigf(fv.y) * c1 + sigf(iv.y) * tanhe(gv.y);
            c1s[u * CP + rr]     = c0;
            c1s[u * CP + rr + 1] = c1;
            *(float2*)(h1s + u * HP + rr) =
                make_float2(sigf(ov.x) * tanhe(c0), sigf(ov.y) * tanhe(c1));
        }
        __syncthreads();                                     // (2) h1_new visible

        // ======== layer 2: acc = b2 + h1_new @ W2 + h2 @ U2 ========
        #pragma unroll
        for (int p = 0; p < 4; p++) {
            acc[0][p] = pack2(b2i, b2i);
            acc[1][p] = pack2(b2f, b2f);
            acc[2][p] = pack2(b2g, b2g);
            acc[3][p] = pack2(b2o, b2o);
        }
        {
            const char* hb1 = (const char*)(h1s + r0);
            const char* hb2 = (const char*)(h2s + r0);
            #pragma unroll 2
            for (int k = 0; k < 256; k++) {
                float4 w = g_w2q[k * 256 + u];
                float4 v = g_u2q[k * 256 + u];
                const ulonglong2* hp1 = (const ulonglong2*)(hb1 + (size_t)k * (HP * 4));
                const ulonglong2* hp2 = (const ulonglong2*)(hb2 + (size_t)k * (HP * 4));
                ulonglong2 a0 = hp1[0], a1 = hp1[1];
                ULL wi = pack2(w.x, w.x), wf = pack2(w.y, w.y);
                ULL wg = pack2(w.z, w.z), wo = pack2(w.w, w.w);
                #pragma unroll
                for (int p = 0; p < 4; p++) {
                    ULL h1v = (p == 0) ? a0.x : (p == 1) ? a0.y : (p == 2) ? a1.x : a1.y;
                    acc[0][p] = fma2(h1v, wi, acc[0][p]);
                    acc[1][p] = fma2(h1v, wf, acc[1][p]);
                    acc[2][p] = fma2(h1v, wg, acc[2][p]);
                    acc[3][p] = fma2(h1v, wo, acc[3][p]);
                }
                ulonglong2 b0 = hp2[0], b1v = hp2[1];
                ULL vi = pack2(v.x, v.x), vf = pack2(v.y, v.y);
                ULL vg = pack2(v.z, v.z), vo = pack2(v.w, v.w);
                #pragma unroll
                for (int p = 0; p < 4; p++) {
                    ULL h2v = (p == 0) ? b0.x : (p == 1) ? b0.y : (p == 2) ? b1v.x : b1v.y;
                    acc[0][p] = fma2(h2v, vi, acc[0][p]);
                    acc[1][p] = fma2(h2v, vf, acc[1][p]);
                    acc[2][p] = fma2(h2v, vg, acc[2][p]);
                    acc[3][p] = fma2(h2v, vo, acc[3][p]);
                }
            }
        }
        __syncthreads();                                     // (3) GEMV2 + proj reads done
        #pragma unroll
        for (int p = 0; p < 4; p++) {
            float2 iv = unpack2(acc[0][p]);
            float2 fv = unpack2(acc[1][p]);
            float2 gv = unpack2(acc[2][p]);
            float2 ov = unpack2(acc[3][p]);
            int rr = r0 + 2 * p;
            float c0 = c2s[u * CP + rr], c1 = c2s[u * CP + rr + 1];
            c0 = sigf(fv.x) * c0 + sigf(iv.x) * tanhe(gv.x);
            c1 = sigf(fv.y) * c1 + sigf(iv.y) * tanhe(gv.y);
            c2s[u * CP + rr]     = c0;
            c2s[u * CP + rr + 1] = c1;
            float2 hn = make_float2(sigf(ov.x) * tanhe(c0), sigf(ov.y) * tanhe(c1));
            *(float2*)(h2s + u * HP + rr) = hn;
            out[((size_t)(rb + rr) * T_STEPS + t) * 256 + u]     = hn.x;
            out[((size_t)(rb + rr + 1) * T_STEPS + t) * 256 + u] = hn.y;
        }
        __syncthreads();                                     // (4) h2_new visible

        // ---- fused mu/logvar projection + sampler (4 rows per thread) ----
        if (pact) {
            ULL amu[2], alv[2];
            amu[0] = amu[1] = alv[0] = alv[1] = 0ULL;
            const char* hb = (const char*)(h2s + pr0);
            #pragma unroll 2
            for (int k = 0; k < 256; k++) {
                float2 wv = g_pw2[k * 80 + pf];
                ULL wmu = pack2(wv.x, wv.x), wlv = pack2(wv.y, wv.y);
                const ulonglong2* hp = (const ulonglong2*)(hb + (size_t)k * (HP * 4));
                ulonglong2 h01 = hp[0];
                amu[0] = fma2(h01.x, wmu, amu[0]);
                alv[0] = fma2(h01.x, wlv, alv[0]);
                amu[1] = fma2(h01.y, wmu, amu[1]);
                alv[1] = fma2(h01.y, wlv, alv[1]);
            }
            #pragma unroll
            for (int q = 0; q < 2; q++) {
                float2 mu = unpack2(amu[q]);
                float2 lv = unpack2(alv[q]);
                mu.x += pbmu; mu.y += pbmu;
                lv.x += pblv; lv.y += pblv;
                int r = pr0 + 2 * q;
                size_t b0 = ((size_t)(rb + r)     * T_STEPS + t) * 80 + pf;
                size_t b1 = ((size_t)(rb + r + 1) * T_STEPS + t) * 80 + pf;
                float e0 = eps[b0], e1 = eps[b1];
                out[41943040u + b0] = mu.x;
                out[41943040u + b1] = mu.y;
                out[55050240u + b0] = lv.x;
                out[55050240u + b1] = lv.y;
                out[68157440u + b0] = e0 * __expf(0.5f * mu.x) + lv.x;
                out[68157440u + b1] = e1 * __expf(0.5f * mu.y) + lv.y;
            }
        }
        // next h1s write is behind barrier (1) of t+1; h2s behind (3). Safe.
    }
}

extern "C" void kernel_launch(void* const* d_in, const int* in_sizes, int n_in,
                              void* d_out, int out_size) {
    // order: x, z1, z2, eps, W1, U1, b1, W2, U2, b2, Wmu, bmu, Wlv, blv
    const float* z1  = (const float*)d_in[1];
    const float* z2  = (const float*)d_in[2];
    const float* eps = (const float*)d_in[3];
    const float* W1  = (const float*)d_in[4];
    const float* U1  = (const float*)d_in[5];
    const float* b1  = (const float*)d_in[6];
    const float* W2  = (const float*)d_in[7];
    const float* U2  = (const float*)d_in[8];
    const float* b2  = (const float*)d_in[9];
    const float* Wmu = (const float*)d_in[10];
    const float* bmu = (const float*)d_in[11];
    const float* Wlv = (const float*)d_in[12];
    const float* blv = (const float*)d_in[13];
    float* out = (float*)d_out;

    cudaFuncSetAttribute(lstm_kernel, cudaFuncAttributeMaxDynamicSharedMemorySize, SMEM_BYTES);

    repack_kernel<<<256, 256>>>(W1, U1, W2, U2, Wmu, Wlv);
    xw1_kernel<<<1024, 256>>>(z1, z2, b1);
    lstm_kernel<<<256, NT, SMEM_BYTES>>>(b2, bmu, blv, eps, out);
}

// round 9
// speedup vs baseline: 1.2018x; 1.2018x over previous
#include <cuda_runtime.h>

// ---------------------------------------------------------------------------
// 2-layer LSTM decoder. Round-9 = Round-4 (proven best, 5785us) + batched
// weight loads (MLP=4) in both GEMV loops, register-budgeted (no rings, no
// occupancy changes). 256 CTAs x 32 rows x 512 threads, 4 barriers/step,
// fused (free) mu/logvar projection + sampler.
// ---------------------------------------------------------------------------

#define ULL unsigned long long
#define T_STEPS 20
#define HP 36   // h row stride (floats): 16B-aligned, broadcast LDS.128 reads
#define CP 33   // c row stride: odd -> conflict-free per-thread access

__device__ __forceinline__ ULL pack2(float x, float y) {
    ULL r; asm("mov.b64 %0, {%1, %2};" : "=l"(r) : "f"(x), "f"(y)); return r;
}
__device__ __forceinline__ float2 unpack2(ULL v) {
    float2 r; asm("mov.b64 {%0, %1}, %2;" : "=f"(r.x), "=f"(r.y) : "l"(v)); return r;
}
__device__ __forceinline__ ULL fma2(ULL a, ULL b, ULL c) {
    ULL d; asm("fma.rn.f32x2 %0, %1, %2, %3;" : "=l"(d) : "l"(a), "l"(b), "l"(c)); return d;
}
__device__ __forceinline__ float sigf(float x)  { return __fdividef(1.f, 1.f + __expf(-x)); }
__device__ __forceinline__ float tanhe(float x) { return __fdividef(2.f, 1.f + __expf(-2.f * x)) - 1.f; }

__device__ float4 g_w1q [64  * 256];          // W1 gate quads  [k][u] = (i,f,g,o)
__device__ float4 g_u1q [256 * 256];          // U1 quads
__device__ float4 g_w2q [256 * 256];          // W2 quads
__device__ float4 g_u2q [256 * 256];          // U2 quads
__device__ float2 g_pw2 [256 * 80 + 80];      // (Wmu, Wlv) pairs [k][f]
__device__ float4 g_xw1q[8192 * 256];         // xw1 quads [row][u], bias folded

__global__ void repack_kernel(const float* __restrict__ W1, const float* __restrict__ U1,
                              const float* __restrict__ W2, const float* __restrict__ U2,
                              const float* __restrict__ Wmu, const float* __restrict__ Wlv) {
    int i = blockIdx.x * blockDim.x + threadIdx.x;   // 0..65535
    int k = i >> 8, u = i & 255;
    const float* r;
    if (i < 64 * 256) {
        r = W1 + k * 1024;
        g_w1q[i] = make_float4(r[u], r[256 + u], r[512 + u], r[768 + u]);
    }
    r = U1 + k * 1024; g_u1q[i] = make_float4(r[u], r[256 + u], r[512 + u], r[768 + u]);
    r = W2 + k * 1024; g_w2q[i] = make_float4(r[u], r[256 + u], r[512 + u], r[768 + u]);
    r = U2 + k * 1024; g_u2q[i] = make_float4(r[u], r[256 + u], r[512 + u], r[768 + u]);
    if (u < 80) g_pw2[k * 80 + u] = make_float2(Wmu[k * 80 + u], Wlv[k * 80 + u]);
}

__global__ void xw1_kernel(const float* __restrict__ z1, const float* __restrict__ z2,
                           const float* __restrict__ b1) {
    __shared__ float zt[8][64];
    const int tid = threadIdx.x;
    const int rb  = blockIdx.x * 8;
    for (int i = tid; i < 512; i += 256) {
        int r = i >> 6, k = i & 63;
        zt[r][k] = (k < 32) ? z1[(rb + r) * 32 + k] : z2[(rb + r) * 32 + (k - 32)];
    }
    __syncthreads();
    const int u = tid;
    float4 acc[8];
    #pragma unroll
    for (int r = 0; r < 8; r++) acc[r] = make_float4(0.f, 0.f, 0.f, 0.f);
    for (int k = 0; k < 64; k++) {
        float4 w = g_w1q[k * 256 + u];
        #pragma unroll
        for (int r = 0; r < 8; r++) {
            float zv = zt[r][k];
            acc[r].x += zv * w.x; acc[r].y += zv * w.y;
            acc[r].z += zv * w.z; acc[r].w += zv * w.w;
        }
    }
    float4 bq = make_float4(b1[u], b1[256 + u], b1[512 + u], b1[768 + u]);
    #pragma unroll
    for (int r = 0; r < 8; r++)
        g_xw1q[(size_t)(rb + r) * 256 + u] =
            make_float4(acc[r].x + bq.x, acc[r].y + bq.y, acc[r].z + bq.z, acc[r].w + bq.w);
}

// SMEM: h1s/h2s [256][HP], c1s/c2s [256][CP]
#define SMEM_FLOATS (2 * 256 * HP + 2 * 256 * CP)
#define SMEM_BYTES  (SMEM_FLOATS * 4)

__global__ void __launch_bounds__(512, 1) lstm_kernel(
    const float* __restrict__ b2, const float* __restrict__ bmu, const float* __restrict__ blv,
    const float* __restrict__ eps, float* __restrict__ out)
{
    extern __shared__ float sm[];
    float* h1s = sm;
    float* h2s = sm + 256 * HP;
    float* c1s = sm + 2 * 256 * HP;
    float* c2s = c1s + 256 * CP;

    const int tid = threadIdx.x;
    const int u   = tid & 255;
    const int rg  = tid >> 8;
    const int r0  = rg * 16;
    const int rb  = blockIdx.x * 32;

    for (int i = tid; i < SMEM_FLOATS; i += 512) sm[i] = 0.f;
    __syncthreads();

    const float b2i = b2[u], b2f = b2[256 + u], b2g = b2[512 + u], b2o = b2[768 + u];

    // fused proj+sampler mapping: 480 threads = 80+80 cols x 3 row groups
    const bool  pact = tid < 320;
    const int   pf   = pact ? (tid % 80) : 0;
    const int   pgp  = pact ? (tid / 80) : 0;
    const int   pr0  = pgp * 8;
    const float pbmu = pact ? bmu[pf] : 0.f;
    const float pblv = pact ? blv[pf] : 0.f;

    const float4* xq = g_xw1q + (size_t)(rb + r0) * 256 + u;

    ULL acc[4][8];

    for (int t = 0; t < T_STEPS; t++) {
        // ================= layer 1: acc = xw1 + h1 @ U1 =================
        #pragma unroll
        for (int p = 0; p < 8; p++) {
            float4 q0 = xq[(2 * p) * 256];
            float4 q1 = xq[(2 * p + 1) * 256];
            acc[0][p] = pack2(q0.x, q1.x);
            acc[1][p] = pack2(q0.y, q1.y);
            acc[2][p] = pack2(q0.z, q1.z);
            acc[3][p] = pack2(q0.w, q1.w);
        }
        {
            const char* hb = (const char*)(h1s + r0);
            #pragma unroll 1
            for (int kb = 0; kb < 256; kb += 4) {
                // batched weight loads: 4 independent LDG.128 (MLP=4)
                float4 wq0 = g_u1q[(kb + 0) * 256 + u];
                float4 wq1 = g_u1q[(kb + 1) * 256 + u];
                float4 wq2 = g_u1q[(kb + 2) * 256 + u];
                float4 wq3 = g_u1q[(kb + 3) * 256 + u];
                #pragma unroll
                for (int j = 0; j < 4; j++) {
                    float4 w = (j == 0) ? wq0 : (j == 1) ? wq1 : (j == 2) ? wq2 : wq3;
                    int k = kb + j;
                    ULL wi = pack2(w.x, w.x), wf = pack2(w.y, w.y);
                    ULL wg = pack2(w.z, w.z), wo = pack2(w.w, w.w);
                    const ulonglong2* hp = (const ulonglong2*)(hb + (size_t)k * (HP * 4));
                    ulonglong2 a0 = hp[0], a1 = hp[1];
                    #pragma unroll
                    for (int p = 0; p < 4; p++) {
                        ULL hv = (p == 0) ? a0.x : (p == 1) ? a0.y : (p == 2) ? a1.x : a1.y;
                        acc[0][p] = fma2(hv, wi, acc[0][p]);
                        acc[1][p] = fma2(hv, wf, acc[1][p]);
                        acc[2][p] = fma2(hv, wg, acc[2][p]);
                        acc[3][p] = fma2(hv, wo, acc[3][p]);
                    }
                    ulonglong2 a2 = hp[2], a3 = hp[3];
                    #pragma unroll
                    for (int p = 4; p < 8; p++) {
                        ULL hv = (p == 4) ? a2.x : (p == 5) ? a2.y : (p == 6) ? a3.x : a3.y;
                        acc[0][p] = fma2(hv, wi, acc[0][p]);
                        acc[1][p] = fma2(hv, wf, acc[1][p]);
                        acc[2][p] = fma2(hv, wg, acc[2][p]);
                        acc[3][p] = fma2(hv, wo, acc[3][p]);
                    }
                }
            }
        }
        __syncthreads();                                     // (1) GEMV1 reads done
        #pragma unroll
        for (int p = 0; p < 8; p++) {
            float2 iv = unpack2(acc[0][p]);
            float2 fv = unpack2(acc[1][p]);
            float2 gv = unpack2(acc[2][p]);
            float2 ov = unpack2(acc[3][p]);
            int rr = r0 + 2 * p;
            float c0 = c1s[u * CP + rr], c1 = c1s[u * CP + rr + 1];
            c0 = sigf(fv.x) * c0 + sigf(iv.x) * tanhe(gv.x);
            c1 = sigf(fv.y) * c1 + sigf(iv.y) * tanhe(gv.y);
            c1s[u * CP + rr]     = c0;
            c1s[u * CP + rr + 1] = c1;
            *(float2*)(h1s + u * HP + rr) =
                make_float2(sigf(ov.x) * tanhe(c0), sigf(ov.y) * tanhe(c1));
        }
        __syncthreads();                                     // (2) h1_new visible

        // ======== layer 2: acc = b2 + h1_new @ W2 + h2 @ U2 ========
        #pragma unroll
        for (int p = 0; p < 8; p++) {
            acc[0][p] = pack2(b2i, b2i);
            acc[1][p] = pack2(b2f, b2f);
            acc[2][p] = pack2(b2g, b2g);
            acc[3][p] = pack2(b2o, b2o);
        }
        {
            const char* hb1 = (const char*)(h1s + r0);
            const char* hb2 = (const char*)(h2s + r0);
            #pragma unroll 1
            for (int kb = 0; kb < 256; kb += 2) {
                // batched: 4 independent LDG.128 per 2-k block (MLP=4)
                float4 wA = g_w2q[(kb + 0) * 256 + u];
                float4 vA = g_u2q[(kb + 0) * 256 + u];
                float4 wB = g_w2q[(kb + 1) * 256 + u];
                float4 vB = g_u2q[(kb + 1) * 256 + u];
                #pragma unroll
                for (int j = 0; j < 2; j++) {
                    float4 w = (j == 0) ? wA : wB;
                    float4 v = (j == 0) ? vA : vB;
                    int k = kb + j;
                    ULL wi = pack2(w.x, w.x), wf = pack2(w.y, w.y);
                    ULL wg = pack2(w.z, w.z), wo = pack2(w.w, w.w);
                    ULL vi = pack2(v.x, v.x), vf = pack2(v.y, v.y);
                    ULL vg = pack2(v.z, v.z), vo = pack2(v.w, v.w);
                    const ulonglong2* hp1 = (const ulonglong2*)(hb1 + (size_t)k * (HP * 4));
                    const ulonglong2* hp2 = (const ulonglong2*)(hb2 + (size_t)k * (HP * 4));
                    {
                        ulonglong2 a0 = hp1[0], a1 = hp1[1];
                        ulonglong2 b0 = hp2[0], b1v = hp2[1];
                        #pragma unroll
                        for (int p = 0; p < 4; p++) {
                            ULL h1v = (p == 0) ? a0.x : (p == 1) ? a0.y : (p == 2) ? a1.x : a1.y;
                            ULL h2v = (p == 0) ? b0.x : (p == 1) ? b0.y : (p == 2) ? b1v.x : b1v.y;
                            acc[0][p] = fma2(h1v, wi, acc[0][p]);
                            acc[1][p] = fma2(h1v, wf, acc[1][p]);
                            acc[2][p] = fma2(h1v, wg, acc[2][p]);
                            acc[3][p] = fma2(h1v, wo, acc[3][p]);
                            acc[0][p] = fma2(h2v, vi, acc[0][p]);
                            acc[1][p] = fma2(h2v, vf, acc[1][p]);
                            acc[2][p] = fma2(h2v, vg, acc[2][p]);
                            acc[3][p] = fma2(h2v, vo, acc[3][p]);
                        }
                    }
                    {
                        ulonglong2 a2 = hp1[2], a3 = hp1[3];
                        ulonglong2 b2v = hp2[2], b3 = hp2[3];
                        #pragma unroll
                        for (int p = 4; p < 8; p++) {
                            ULL h1v = (p == 4) ? a2.x : (p == 5) ? a2.y : (p == 6) ? a3.x : a3.y;
                            ULL h2v = (p == 4) ? b2v.x : (p == 5) ? b2v.y : (p == 6) ? b3.x : b3.y;
                            acc[0][p] = fma2(h1v, wi, acc[0][p]);
                            acc[1][p] = fma2(h1v, wf, acc[1][p]);
                            acc[2][p] = fma2(h1v, wg, acc[2][p]);
                            acc[3][p] = fma2(h1v, wo, acc[3][p]);
                            acc[0][p] = fma2(h2v, vi, acc[0][p]);
                            acc[1][p] = fma2(h2v, vf, acc[1][p]);
                            acc[2][p] = fma2(h2v, vg, acc[2][p]);
                            acc[3][p] = fma2(h2v, vo, acc[3][p]);
                        }
                    }
                }
            }
        }
        __syncthreads();                                     // (3) GEMV2 + proj reads done
        #pragma unroll
        for (int p = 0; p < 8; p++) {
            float2 iv = unpack2(acc[0][p]);
            float2 fv = unpack2(acc[1][p]);
            float2 gv = unpack2(acc[2][p]);
            float2 ov = unpack2(acc[3][p]);
            int rr = r0 + 2 * p;
            float c0 = c2s[u * CP + rr], c1 = c2s[u * CP + rr + 1];
            c0 = sigf(fv.x) * c0 + sigf(iv.x) * tanhe(gv.x);
            c1 = sigf(fv.y) * c1 + sigf(iv.y) * tanhe(gv.y);
            c2s[u * CP + rr]     = c0;
            c2s[u * CP + rr + 1] = c1;
            float2 hn = make_float2(sigf(ov.x) * tanhe(c0), sigf(ov.y) * tanhe(c1));
            *(float2*)(h2s + u * HP + rr) = hn;
            out[((size_t)(rb + rr) * T_STEPS + t) * 256 + u]     = hn.x;
            out[((size_t)(rb + rr + 1) * T_STEPS + t) * 256 + u] = hn.y;
        }
        __syncthreads();                                     // (4) h2_new visible

        // ---- fused mu/logvar projection + sampler (320 threads, 8 rows each) ----
        if (pact) {
            ULL amu[4], alv[4];
            #pragma unroll
            for (int q = 0; q < 4; q++) { amu[q] = 0ULL; alv[q] = 0ULL; }
            const char* hb = (const char*)(h2s + pr0);
            #pragma unroll 2
            for (int k = 0; k < 256; k++) {
                float2 wv = g_pw2[k * 80 + pf];
                ULL wmu = pack2(wv.x, wv.x), wlv = pack2(wv.y, wv.y);
                const ulonglong2* hp = (const ulonglong2*)(hb + (size_t)k * (HP * 4));
                ulonglong2 h01 = hp[0], h23 = hp[1];
                #pragma unroll
                for (int q = 0; q < 4; q++) {
                    ULL hv = (q == 0) ? h01.x : (q == 1) ? h01.y : (q == 2) ? h23.x : h23.y;
                    amu[q] = fma2(hv, wmu, amu[q]);
                    alv[q] = fma2(hv, wlv, alv[q]);
                }
            }
            #pragma unroll
            for (int q = 0; q < 4; q++) {
                float2 mu = unpack2(amu[q]);
                float2 lv = unpack2(alv[q]);
                mu.x += pbmu; mu.y += pbmu;
                lv.x += pblv; lv.y += pblv;
                int r = pr0 + 2 * q;
                size_t b0 = ((size_t)(rb + r)     * T_STEPS + t) * 80 + pf;
                size_t b1 = ((size_t)(rb + r + 1) * T_STEPS + t) * 80 + pf;
                float e0 = eps[b0], e1 = eps[b1];
                out[41943040u + b0] = mu.x;
                out[41943040u + b1] = mu.y;
                out[55050240u + b0] = lv.x;
                out[55050240u + b1] = lv.y;
                out[68157440u + b0] = e0 * __expf(0.5f * mu.x) + lv.x;
                out[68157440u + b1] = e1 * __expf(0.5f * mu.y) + lv.y;
            }
        }
        // next h1s write is behind barrier (1) of t+1; h2s behind (3). Safe.
    }
}

extern "C" void kernel_launch(void* const* d_in, const int* in_sizes, int n_in,
                              void* d_out, int out_size) {
    // order: x, z1, z2, eps, W1, U1, b1, W2, U2, b2, Wmu, bmu, Wlv, blv
    const float* z1  = (const float*)d_in[1];
    const float* z2  = (const float*)d_in[2];
    const float* eps = (const float*)d_in[3];
    const float* W1  = (const float*)d_in[4];
    const float* U1  = (const float*)d_in[5];
    const float* b1  = (const float*)d_in[6];
    const float* W2  = (const float*)d_in[7];
    const float* U2  = (const float*)d_in[8];
    const float* b2  = (const float*)d_in[9];
    const float* Wmu = (const float*)d_in[10];
    const float* bmu = (const float*)d_in[11];
    const float* Wlv = (const float*)d_in[12];
    const float* blv = (const float*)d_in[13];
    float* out = (float*)d_out;

    cudaFuncSetAttribute(lstm_kernel, cudaFuncAttributeMaxDynamicSharedMemorySize, SMEM_BYTES);

    repack_kernel<<<256, 256>>>(W1, U1, W2, U2, Wmu, Wlv);
    xw1_kernel<<<1024, 256>>>(z1, z2, b1);
    lstm_kernel<<<256, 512, SMEM_BYTES>>>(b2, bmu, blv, eps, out);
}